// round 6
// baseline (speedup 1.0000x reference)
#include <cuda_runtime.h>
#include <cstdint>

// ===========================================================================
// VQ-VAE quantizer — fp32 FFMA2 argmin-GEMM, occupancy-optimized.
//   x [4,64,32,32,32] fp32, weight [512,64] fp32
//   out: quantized_st (8.4M), embed_idx (131072, as float), latent_loss (1)
//
// argmin_j ||x-w_j||^2 == argmin_j ( wsq_j - 2 x.w_j )
// Round 6: M=1 / 512 threads (4 warps/SMSP, regs ~90) instead of M=2 / 256
// threads (2 warps/SMSP, regs 190). Same FFMA2 inner product association as
// rounds 2/3 (argmin bit-stable). wsq fetched as float4 per 4 codes.
// ===========================================================================

#define FMA_F32X2(d, a, b, c) \
    asm("fma.rn.f32x2 %0, %1, %2, %3;" : "=l"(d) : "l"(a), "l"(b), "l"(c))
#define ADD_F32X2(d, a, b) \
    asm("add.rn.f32x2 %0, %1, %2;" : "=l"(d) : "l"(a), "l"(b))
#define PACK_F32X2(d, lo, hi) \
    asm("mov.b64 %0, {%1, %2};" : "=l"(d) : "f"(lo), "f"(hi))
#define UNPACK_F32X2(lo, hi, v) \
    asm("mov.b64 {%0, %1}, %2;" : "=f"(lo), "=f"(hi) : "l"(v))

static constexpr int C  = 64;     // embed dim
static constexpr int E  = 512;    // codebook entries
static constexpr int S  = 32768;  // spatial positions per batch
static constexpr int RP = 68;     // padded codebook row (floats)

static constexpr int THREADS = 512;

__device__ float g_partials[512];

// ---------------------------------------------------------------------------
// Main kernel: one thread = one position. Codebook + wsq in smem (~141 KB).
// ---------------------------------------------------------------------------
__global__ void __launch_bounds__(THREADS, 1) vq_fused_kernel(
    const float* __restrict__ x, const float* __restrict__ w,
    float* __restrict__ out_q, float* __restrict__ out_idx)
{
    extern __shared__ float smem[];
    float* ws  = smem;            // [E][RP]
    float* wsq = smem + E * RP;   // [E] (16B aligned: E*RP = 34816 floats)

    const int tid = threadIdx.x;

    // cooperative codebook load into padded rows
    for (int i = tid; i < E * C / 4; i += THREADS) {
        const int j = i >> 4;
        const int k = i & 15;
        ((float4*)(ws + j * RP))[k] = ((const float4*)w)[i];
    }
    __syncthreads();

    // wsq[j] (one code per thread)
    {
        const int j = tid;
        float ssum = 0.f;
        #pragma unroll
        for (int c = 0; c < C; ++c) {
            const float v = ws[j * RP + c];
            ssum = fmaf(v, v, ssum);
        }
        wsq[j] = ssum;
    }
    __syncthreads();

    const int p = blockIdx.x * THREADS + tid;
    const int b = p >> 15;
    const int s = p & (S - 1);
    const float* xp = x + (size_t)b * C * S + s;

    // load 64 channels of this position into packed f32x2 registers
    unsigned long long xv[C / 2];
    #pragma unroll
    for (int k = 0; k < C / 2; ++k) {
        const float lo = xp[(size_t)(2 * k) * S];
        const float hi = xp[(size_t)(2 * k + 1) * S];
        PACK_F32X2(xv[k], lo, hi);
    }

    float best = 3.4e38f;
    int bestj = 0;

    const float4* wsq4 = (const float4*)wsq;

    #pragma unroll 1
    for (int j4 = 0; j4 < E / 4; ++j4) {
        const float4 wq = wsq4[j4];
        const float wqa[4] = {wq.x, wq.y, wq.z, wq.w};
        #pragma unroll
        for (int u = 0; u < 4; ++u) {
            const int j = j4 * 4 + u;
            const ulonglong2* wrow = (const ulonglong2*)(ws + j * RP);
            unsigned long long a0 = 0ull, a1 = 0ull, a2 = 0ull, a3 = 0ull;
            #pragma unroll
            for (int k = 0; k < C / 4; ++k) {   // 16x: LDS.128 + 2 FFMA2
                const ulonglong2 wv = wrow[k];
                if ((k & 1) == 0) {
                    FMA_F32X2(a0, xv[2 * k],     wv.x, a0);
                    FMA_F32X2(a1, xv[2 * k + 1], wv.y, a1);
                } else {
                    FMA_F32X2(a2, xv[2 * k],     wv.x, a2);
                    FMA_F32X2(a3, xv[2 * k + 1], wv.y, a3);
                }
            }
            unsigned long long s01, s23, sA;
            ADD_F32X2(s01, a0, a1);
            ADD_F32X2(s23, a2, a3);
            ADD_F32X2(sA, s01, s23);
            float lo, hi;
            UNPACK_F32X2(lo, hi, sA);
            const float d = fmaf(-2.f, lo + hi, wqa[u]);
            if (d < best) { best = d; bestj = j; }   // strict <: first-min tie rule
        }
    }

    out_idx[p] = (float)bestj;

    // fused epilogue: q = fl(fl(w-x)+x), loss partial
    float acc = 0.f;
    const float* wr = ws + bestj * RP;
    float* qp = out_q + (size_t)b * C * S + s;
    #pragma unroll
    for (int k = 0; k < C / 2; ++k) {
        float xlo, xhi;
        UNPACK_F32X2(xlo, xhi, xv[k]);
        const float d0 = wr[2 * k]     - xlo;
        const float d1 = wr[2 * k + 1] - xhi;
        qp[(size_t)(2 * k) * S]     = d0 + xlo;
        qp[(size_t)(2 * k + 1) * S] = d1 + xhi;
        acc = fmaf(d0, d0, acc);
        acc = fmaf(d1, d1, acc);
    }

    // block loss reduction (reuse smem codebook area — all reads done)
    __syncthreads();
    float* red = smem;
    red[tid] = acc;
    __syncthreads();
    #pragma unroll
    for (int off = THREADS / 2; off > 0; off >>= 1) {
        if (tid < off) red[tid] += red[tid + off];
        __syncthreads();
    }
    if (tid == 0) g_partials[blockIdx.x] = red[0];
}

// ---------------------------------------------------------------------------
__global__ void __launch_bounds__(256) loss_final_kernel(
    float* __restrict__ out_loss, int nblocks, float inv_n)
{
    __shared__ float red[256];
    const int tid = threadIdx.x;
    float a = 0.f;
    for (int i = tid; i < nblocks; i += 256) a += g_partials[i];
    red[tid] = a;
    __syncthreads();
    #pragma unroll
    for (int off = 128; off > 0; off >>= 1) {
        if (tid < off) red[tid] += red[tid + off];
        __syncthreads();
    }
    if (tid == 0) out_loss[0] = 0.25f * red[0] * inv_n;
}

// ---------------------------------------------------------------------------
extern "C" void kernel_launch(void* const* d_in, const int* in_sizes, int n_in,
                              void* d_out, int out_size)
{
    const float* x = (const float*)d_in[0];
    const float* w = (const float*)d_in[1];
    float* out = (float*)d_out;

    const int n_x  = in_sizes[0];   // 8388608
    const int npos = n_x / C;       // 131072

    float* out_q    = out;
    float* out_idx  = out + n_x;
    float* out_loss = out + n_x + npos;

    const int smem_bytes = (E * RP + E) * (int)sizeof(float);  // 141312 B
    cudaFuncSetAttribute(vq_fused_kernel,
                         cudaFuncAttributeMaxDynamicSharedMemorySize, smem_bytes);

    const int blocks = npos / THREADS;   // 256
    vq_fused_kernel<<<blocks, THREADS, smem_bytes>>>(x, w, out_q, out_idx);
    loss_final_kernel<<<1, 256>>>(out_loss, blocks, 1.0f / (float)n_x);
}

// round 7
// speedup vs baseline: 1.9515x; 1.9515x over previous
#include <cuda_runtime.h>
#include <cstdint>

// ===========================================================================
// VQ-VAE quantizer — fp32 FFMA2 argmin-GEMM, software-pipelined LDS.
//   x [4,64,32,32,32] fp32, weight [512,64] fp32
//   out: quantized_st (8.4M), embed_idx (131072, as float), latent_loss (1)
//
// argmin_j ||x-w_j||^2 == argmin_j ( wsq_j - 2 x.w_j )
// Round 7: M=2 / 256 threads (round-3 config, best so far) + explicit
// half-row ping-pong prefetch: 8 LDS.128 in flight under 32 FFMA2.
// Dot association identical to rounds 2/3 (argmin bit-stable).
// ===========================================================================

#define FMA_F32X2(d, a, b, c) \
    asm("fma.rn.f32x2 %0, %1, %2, %3;" : "=l"(d) : "l"(a), "l"(b), "l"(c))
#define ADD_F32X2(d, a, b) \
    asm("add.rn.f32x2 %0, %1, %2;" : "=l"(d) : "l"(a), "l"(b))
#define PACK_F32X2(d, lo, hi) \
    asm("mov.b64 %0, {%1, %2};" : "=l"(d) : "f"(lo), "f"(hi))
#define UNPACK_F32X2(lo, hi, v) \
    asm("mov.b64 {%0, %1}, %2;" : "=f"(lo), "=f"(hi) : "l"(v))

static constexpr int C  = 64;     // embed dim
static constexpr int E  = 512;    // codebook entries
static constexpr int S  = 32768;  // spatial positions per batch
static constexpr int RP = 68;     // padded codebook row (floats)

static constexpr int THREADS = 256;

__device__ float g_partials[256];

// ---------------------------------------------------------------------------
__global__ void __launch_bounds__(THREADS, 1) vq_fused_kernel(
    const float* __restrict__ x, const float* __restrict__ w,
    float* __restrict__ out_q, float* __restrict__ out_idx)
{
    extern __shared__ float smem[];
    float* ws  = smem;                  // [E+1][RP] (+1 pad row for prefetch)
    float* wsq = smem + (E + 1) * RP;   // [E]

    const int tid = threadIdx.x;

    // cooperative codebook load into padded rows
    for (int i = tid; i < E * C / 4; i += THREADS) {
        const int j = i >> 4;
        const int k = i & 15;
        ((float4*)(ws + j * RP))[k] = ((const float4*)w)[i];
    }
    // zero the pad row (row E) so prefetch reads are defined
    for (int k = tid; k < RP; k += THREADS) ws[E * RP + k] = 0.f;
    __syncthreads();

    // wsq
    for (int j = tid; j < E; j += THREADS) {
        float ssum = 0.f;
        #pragma unroll
        for (int c = 0; c < C; ++c) {
            const float v = ws[j * RP + c];
            ssum = fmaf(v, v, ssum);
        }
        wsq[j] = ssum;
    }
    __syncthreads();

    const int p0 = blockIdx.x * 512 + tid;
    const int p1 = p0 + 256;
    const int b0 = p0 >> 15, s0 = p0 & (S - 1);
    const int b1 = p1 >> 15, s1 = p1 & (S - 1);
    const float* xp0 = x + (size_t)b0 * C * S + s0;
    const float* xp1 = x + (size_t)b1 * C * S + s1;

    unsigned long long xv0[C / 2], xv1[C / 2];
    #pragma unroll
    for (int k = 0; k < C / 2; ++k) {
        float lo = xp0[(size_t)(2 * k) * S];
        float hi = xp0[(size_t)(2 * k + 1) * S];
        PACK_F32X2(xv0[k], lo, hi);
        lo = xp1[(size_t)(2 * k) * S];
        hi = xp1[(size_t)(2 * k + 1) * S];
        PACK_F32X2(xv1[k], lo, hi);
    }

    float best0 = 3.4e38f, best1 = 3.4e38f;
    int bestj0 = 0, bestj1 = 0;

    // ---- ping-pong half-row buffers (8 x 16B each) ----
    ulonglong2 bufA[8], bufB[8];

    // FMA on half H of a buffer; k-parity chain assignment matches rounds 2/3
    #define FMA_HALF(BUF, H)                                                   \
        _Pragma("unroll")                                                      \
        for (int k = 0; k < 8; ++k) {                                          \
            const int kk = (H) * 8 + k;                                        \
            const unsigned long long wx = (BUF)[k].x, wy = (BUF)[k].y;         \
            if ((kk & 1) == 0) {                                               \
                FMA_F32X2(a0, xv0[2 * kk],     wx, a0);                        \
                FMA_F32X2(a1, xv0[2 * kk + 1], wy, a1);                        \
                FMA_F32X2(c0, xv1[2 * kk],     wx, c0);                        \
                FMA_F32X2(c1, xv1[2 * kk + 1], wy, c1);                        \
            } else {                                                           \
                FMA_F32X2(a2, xv0[2 * kk],     wx, a2);                        \
                FMA_F32X2(a3, xv0[2 * kk + 1], wy, a3);                        \
                FMA_F32X2(c2, xv1[2 * kk],     wx, c2);                        \
                FMA_F32X2(c3, xv1[2 * kk + 1], wy, c3);                        \
            }                                                                  \
        }

    #define LOAD_HALF(BUF, ROW, H)                                             \
        {                                                                      \
            const ulonglong2* _wp =                                            \
                (const ulonglong2*)(ws + (ROW) * RP) + (H) * 8;                \
            _Pragma("unroll")                                                  \
            for (int k = 0; k < 8; ++k) (BUF)[k] = _wp[k];                     \
        }

    LOAD_HALF(bufA, 0, 0)   // preload j=0 half0

    #pragma unroll 1
    for (int j = 0; j < E; ++j) {
        unsigned long long a0 = 0ull, a1 = 0ull, a2 = 0ull, a3 = 0ull;
        unsigned long long c0 = 0ull, c1 = 0ull, c2 = 0ull, c3 = 0ull;

        LOAD_HALF(bufB, j, 1)        // half1 of current row in flight...
        FMA_HALF(bufA, 0)            // ...under half0 compute
        LOAD_HALF(bufA, j + 1, 0)    // next row's half0 in flight...
        FMA_HALF(bufB, 1)            // ...under half1 compute

        const float wq = wsq[j];
        {
            unsigned long long s01, s23, sA;
            ADD_F32X2(s01, a0, a1);
            ADD_F32X2(s23, a2, a3);
            ADD_F32X2(sA, s01, s23);
            float lo, hi;
            UNPACK_F32X2(lo, hi, sA);
            const float d = fmaf(-2.f, lo + hi, wq);
            if (d < best0) { best0 = d; bestj0 = j; }
        }
        {
            unsigned long long s01, s23, sA;
            ADD_F32X2(s01, c0, c1);
            ADD_F32X2(s23, c2, c3);
            ADD_F32X2(sA, s01, s23);
            float lo, hi;
            UNPACK_F32X2(lo, hi, sA);
            const float d = fmaf(-2.f, lo + hi, wq);
            if (d < best1) { best1 = d; bestj1 = j; }
        }
    }
    #undef FMA_HALF
    #undef LOAD_HALF

    out_idx[p0] = (float)bestj0;
    out_idx[p1] = (float)bestj1;

    // fused epilogue: q = fl(fl(w-x)+x), loss partials
    float acc = 0.f;
    const float* wr0 = ws + bestj0 * RP;
    const float* wr1 = ws + bestj1 * RP;
    float* q0 = out_q + (size_t)b0 * C * S + s0;
    float* q1 = out_q + (size_t)b1 * C * S + s1;
    #pragma unroll
    for (int k = 0; k < C / 2; ++k) {
        float x0lo, x0hi, x1lo, x1hi;
        UNPACK_F32X2(x0lo, x0hi, xv0[k]);
        UNPACK_F32X2(x1lo, x1hi, xv1[k]);

        const float d00 = wr0[2 * k]     - x0lo;
        const float d01 = wr0[2 * k + 1] - x0hi;
        const float d10 = wr1[2 * k]     - x1lo;
        const float d11 = wr1[2 * k + 1] - x1hi;

        q0[(size_t)(2 * k) * S]     = d00 + x0lo;
        q0[(size_t)(2 * k + 1) * S] = d01 + x0hi;
        q1[(size_t)(2 * k) * S]     = d10 + x1lo;
        q1[(size_t)(2 * k + 1) * S] = d11 + x1hi;

        acc = fmaf(d00, d00, acc);
        acc = fmaf(d01, d01, acc);
        acc = fmaf(d10, d10, acc);
        acc = fmaf(d11, d11, acc);
    }

    // block loss reduction (smem codebook reads all done)
    __syncthreads();
    float* red = smem;
    red[tid] = acc;
    __syncthreads();
    #pragma unroll
    for (int off = THREADS / 2; off > 0; off >>= 1) {
        if (tid < off) red[tid] += red[tid + off];
        __syncthreads();
    }
    if (tid == 0) g_partials[blockIdx.x] = red[0];
}

// ---------------------------------------------------------------------------
__global__ void __launch_bounds__(256) loss_final_kernel(
    float* __restrict__ out_loss, int nblocks, float inv_n)
{
    __shared__ float red[256];
    const int tid = threadIdx.x;
    float a = 0.f;
    for (int i = tid; i < nblocks; i += 256) a += g_partials[i];
    red[tid] = a;
    __syncthreads();
    #pragma unroll
    for (int off = 128; off > 0; off >>= 1) {
        if (tid < off) red[tid] += red[tid + off];
        __syncthreads();
    }
    if (tid == 0) out_loss[0] = 0.25f * red[0] * inv_n;
}

// ---------------------------------------------------------------------------
extern "C" void kernel_launch(void* const* d_in, const int* in_sizes, int n_in,
                              void* d_out, int out_size)
{
    const float* x = (const float*)d_in[0];
    const float* w = (const float*)d_in[1];
    float* out = (float*)d_out;

    const int n_x  = in_sizes[0];   // 8388608
    const int npos = n_x / C;       // 131072

    float* out_q    = out;
    float* out_idx  = out + n_x;
    float* out_loss = out + n_x + npos;

    const int smem_bytes = ((E + 1) * RP + E) * (int)sizeof(float);  // 141584 B
    cudaFuncSetAttribute(vq_fused_kernel,
                         cudaFuncAttributeMaxDynamicSharedMemorySize, smem_bytes);

    const int blocks = npos / 512;   // 256
    vq_fused_kernel<<<blocks, THREADS, smem_bytes>>>(x, w, out_q, out_idx);
    loss_final_kernel<<<1, 256>>>(out_loss, blocks, 1.0f / (float)n_x);
}

// round 8
// speedup vs baseline: 2.5184x; 1.2905x over previous
#include <cuda_runtime.h>
#include <cstdint>

// ===========================================================================
// VQ-VAE quantizer — 3xTF32 mma.sync argmin-GEMM, pipelined (round 8).
//   x [4,64,32,32,32] fp32, weight [512,64] fp32
// out: quantized_st (8.4M), embed_idx (131072 as float), latent_loss (1)
//
// score_j = wsq_j - 2*dot(x,w_j); dot = Ahi*Bhi + Ahi*Blo + Alo*Bhi (3xTF32).
// Block: 512 thr / 16 warps; warp = one m16 tile (16 positions); block tile
// 256 positions; codes in 4 smem chunks of 128 (hi/lo interleaved -> one
// LDS.128 feeds 3 MMAs); 3 independent accumulators per n8 tile.
// ===========================================================================

static constexpr int C = 64, E = 512, S = 32768;

__device__ float g_partials[512];

__device__ __forceinline__ uint32_t f2tf32(float v) {
    uint32_t r;
    asm("cvt.rna.tf32.f32 %0, %1;" : "=r"(r) : "f"(v));
    return r;
}

#define MMA_TF32(acc, a, b0, b1) \
    asm volatile("mma.sync.aligned.m16n8k8.row.col.f32.tf32.tf32.f32 " \
                 "{%0,%1,%2,%3}, {%4,%5,%6,%7}, {%8,%9}, {%0,%1,%2,%3};" \
                 : "+f"((acc)[0]), "+f"((acc)[1]), "+f"((acc)[2]), "+f"((acc)[3]) \
                 : "r"((a)[0]), "r"((a)[1]), "r"((a)[2]), "r"((a)[3]), \
                   "r"(b0), "r"(b1))

// ---- smem layout (float offsets) ----
static constexpr int OFF_XS  = 0;                    // [256][65]
static constexpr int OFF_B   = 16640;                // 16nt*8ks*32lane*4 = 16384
static constexpr int OFF_WSQ = OFF_B + 16384;        // [512]
static constexpr int OFF_IDX = OFF_WSQ + 512;        // [256] int
static constexpr int OFF_RED = OFF_IDX + 256;        // [512]
static constexpr int SMEM_FLOATS = OFF_RED + 512;    // 34304 -> 137216 B

// ===========================================================================
__global__ void __launch_bounds__(512, 1) vq_hmma_kernel(
    const float* __restrict__ x, const float* __restrict__ w,
    float* __restrict__ out_q, float* __restrict__ out_idx)
{
    extern __shared__ float smem[];
    float* xs   = smem + OFF_XS;
    uint4* bbuf = (uint4*)(smem + OFF_B);
    float* wsqs = smem + OFF_WSQ;
    int*   idxb = (int*)(smem + OFF_IDX);
    float* redb = smem + OFF_RED;

    const int tid = threadIdx.x;
    const int l   = tid & 31;
    const int wid = tid >> 5;           // 0..15
    const int wp  = wid * 16;           // warp's first position (local)

    const int p0 = blockIdx.x * 256;
    const int b  = p0 >> 15;
    const int s0 = p0 & (S - 1);
    const float* xb = x + (size_t)b * C * S + s0;

    // ---- x tile -> smem [pos][ch], coalesced ----
    #pragma unroll
    for (int it = 0; it < 32; ++it) {
        const int e  = it * 512 + tid;
        const int k  = e >> 8;
        const int pl = e & 255;
        xs[pl * 65 + k] = xb[(size_t)k * S + pl];
    }
    // ---- wsq (one code per thread) ----
    {
        const float4* wr = (const float4*)(w + tid * C);
        float s = 0.f;
        #pragma unroll
        for (int q = 0; q < 16; ++q) {
            const float4 f = wr[q];
            s = fmaf(f.x, f.x, s); s = fmaf(f.y, f.y, s);
            s = fmaf(f.z, f.z, s); s = fmaf(f.w, f.w, s);
        }
        wsqs[tid] = s;
    }
    __syncthreads();

    // ---- A fragments (tf32 hi/lo), resident ----
    uint32_t Ahi[8][4], Alo[8][4];
    {
        const int r0 = wp + (l >> 2);
        const int r1 = r0 + 8;
        #pragma unroll
        for (int ks = 0; ks < 8; ++ks) {
            const int k0 = ks * 8 + (l & 3);
            const int k1 = k0 + 4;
            const float raw[4] = { xs[r0 * 65 + k0], xs[r1 * 65 + k0],
                                   xs[r0 * 65 + k1], xs[r1 * 65 + k1] };
            #pragma unroll
            for (int i = 0; i < 4; ++i) {
                Ahi[ks][i] = f2tf32(raw[i]);
                Alo[ks][i] = f2tf32(raw[i] - __uint_as_float(Ahi[ks][i]));
            }
        }
    }

    float bv0 = 3.4e38f, bv1 = 3.4e38f;
    int   bj0 = 0,       bj1 = 0;

    // ---- 4 chunks of 128 codes ----
    #pragma unroll 1
    for (int chunk = 0; chunk < 4; ++chunk) {
        const int base = chunk * 128;
        __syncthreads();   // previous chunk's readers done

        // fill B: slot = (nt*8+ks)*32+lane ; [hi(k0),hi(k0+4),lo(k0),lo(k0+4)]
        #pragma unroll
        for (int it = 0; it < 8; ++it) {
            const int slot = it * 512 + tid;
            const int lane = slot & 31;
            const int ks   = (slot >> 5) & 7;
            const int nt   = slot >> 8;
            const int code = base + nt * 8 + (lane >> 2);
            const int k0   = ks * 8 + (lane & 3);
            const float v0 = w[code * C + k0];
            const float v1 = w[code * C + k0 + 4];
            const uint32_t h0 = f2tf32(v0), h1 = f2tf32(v1);
            bbuf[slot] = make_uint4(h0, h1,
                                    f2tf32(v0 - __uint_as_float(h0)),
                                    f2tf32(v1 - __uint_as_float(h1)));
        }
        __syncthreads();

        #pragma unroll 1
        for (int nt = 0; nt < 16; ++nt) {
            float accA[4] = {0.f, 0.f, 0.f, 0.f};   // hi*hi
            float accB[4] = {0.f, 0.f, 0.f, 0.f};   // hi*lo
            float accC[4] = {0.f, 0.f, 0.f, 0.f};   // lo*hi
            #pragma unroll
            for (int ks = 0; ks < 8; ++ks) {
                const uint4 bq = bbuf[(nt * 8 + ks) * 32 + l];
                MMA_TF32(accA, Ahi[ks], bq.x, bq.y);
                MMA_TF32(accB, Ahi[ks], bq.z, bq.w);
                MMA_TF32(accC, Alo[ks], bq.x, bq.y);
            }
            // fold: scores for 2 codes x 2 position-rows
            const int cb = base + nt * 8 + ((l & 3) << 1);
            const float wq0 = wsqs[cb], wq1 = wsqs[cb + 1];
            const float d0 = accA[0] + accB[0] + accC[0];
            const float d1 = accA[1] + accB[1] + accC[1];
            const float d2 = accA[2] + accB[2] + accC[2];
            const float d3 = accA[3] + accB[3] + accC[3];
            const float sc0 = fmaf(-2.f, d0, wq0);
            const float sc1 = fmaf(-2.f, d1, wq1);
            const float sc2 = fmaf(-2.f, d2, wq0);
            const float sc3 = fmaf(-2.f, d3, wq1);
            // row l/4 : sc0 (cb), sc1 (cb+1)
            {
                const int   jm = (sc1 < sc0) ? cb + 1 : cb;   // tie -> lower j
                const float sm = fminf(sc0, sc1);
                bj0 = (sm < bv0) ? jm : bj0;                  // tie -> keep earlier
                bv0 = fminf(bv0, sm);
            }
            // row l/4+8 : sc2, sc3
            {
                const int   jm = (sc3 < sc2) ? cb + 1 : cb;
                const float sm = fminf(sc2, sc3);
                bj1 = (sm < bv1) ? jm : bj1;
                bv1 = fminf(bv1, sm);
            }
        }
    }

    // ---- cross-lane argmin over the quad (cols split across l%4) ----
    #pragma unroll
    for (int off = 1; off <= 2; off <<= 1) {
        float ov; int oj;
        ov = __shfl_xor_sync(0xffffffffu, bv0, off);
        oj = __shfl_xor_sync(0xffffffffu, bj0, off);
        if (ov < bv0 || (ov == bv0 && oj < bj0)) { bv0 = ov; bj0 = oj; }
        ov = __shfl_xor_sync(0xffffffffu, bv1, off);
        oj = __shfl_xor_sync(0xffffffffu, bj1, off);
        if (ov < bv1 || (ov == bv1 && oj < bj1)) { bv1 = ov; bj1 = oj; }
    }
    if ((l & 3) == 0) {
        idxb[wp + (l >> 2)]     = bj0;
        idxb[wp + (l >> 2) + 8] = bj1;
    }
    __syncthreads();

    // ---- epilogue: 2 threads per position, 32 channels each ----
    const int pos = tid & 255;
    const int co  = (tid >> 8) * 32;
    const int j   = idxb[pos];
    if (tid < 256) out_idx[p0 + pos] = (float)j;

    float acc = 0.f;
    const float4* wr = (const float4*)(w + j * C + co);
    float* qb = out_q + (size_t)b * C * S + (size_t)co * S + s0 + pos;
    #pragma unroll
    for (int q4 = 0; q4 < 8; ++q4) {
        const float4 f = wr[q4];
        const float qv[4] = {f.x, f.y, f.z, f.w};
        #pragma unroll
        for (int u = 0; u < 4; ++u) {
            const int c = q4 * 4 + u;
            const float xv = xs[pos * 65 + co + c];
            const float d = qv[u] - xv;
            qb[(size_t)c * S] = d + xv;    // fl(fl(w-x)+x)
            acc = fmaf(d, d, acc);
        }
    }

    redb[tid] = acc;
    __syncthreads();
    #pragma unroll
    for (int off = 256; off > 0; off >>= 1) {
        if (tid < off) redb[tid] += redb[tid + off];
        __syncthreads();
    }
    if (tid == 0) g_partials[blockIdx.x] = redb[0];
}

// ---------------------------------------------------------------------------
__global__ void __launch_bounds__(256) loss_final_kernel(
    float* __restrict__ out_loss, int nblocks, float inv_n)
{
    __shared__ float red[256];
    const int tid = threadIdx.x;
    float a = 0.f;
    for (int i = tid; i < nblocks; i += 256) a += g_partials[i];
    red[tid] = a;
    __syncthreads();
    #pragma unroll
    for (int off = 128; off > 0; off >>= 1) {
        if (tid < off) red[tid] += red[tid + off];
        __syncthreads();
    }
    if (tid == 0) out_loss[0] = 0.25f * red[0] * inv_n;
}

// ---------------------------------------------------------------------------
extern "C" void kernel_launch(void* const* d_in, const int* in_sizes, int n_in,
                              void* d_out, int out_size)
{
    const float* x = (const float*)d_in[0];
    const float* w = (const float*)d_in[1];
    float* out = (float*)d_out;

    const int n_x  = in_sizes[0];   // 8388608
    const int npos = n_x / C;       // 131072

    float* out_q    = out;
    float* out_idx  = out + n_x;
    float* out_loss = out + n_x + npos;

    const int smem_bytes = SMEM_FLOATS * (int)sizeof(float);  // 137216
    cudaFuncSetAttribute(vq_hmma_kernel,
                         cudaFuncAttributeMaxDynamicSharedMemorySize, smem_bytes);

    const int blocks = npos / 256;   // 512
    vq_hmma_kernel<<<blocks, 512, smem_bytes>>>(x, w, out_q, out_idx);
    loss_final_kernel<<<1, 256>>>(out_loss, blocks, 1.0f / (float)n_x);
}

// round 9
// speedup vs baseline: 3.4565x; 1.3725x over previous
#include <cuda_runtime.h>
#include <cuda_fp16.h>
#include <cstdint>

// ===========================================================================
// VQ-VAE quantizer — fp16 2-split mma.sync m16n8k16 argmin-GEMM (round 9).
//   x [4,64,32,32,32] fp32, weight [512,64] fp32
// out: quantized_st (8.4M), embed_idx (131072 as float), latent_loss (1)
//
// score_j = wsq_j - 2*dot(x,w_j); dot = Ahi*Bhi + Ahi*Blo + Alo*Bhi where
// v = hi + lo, hi = fp16(v), lo = fp16(v - hi). Dropped Alo*Blo <= 2^-22|a||b|
// (fp32-rounding class). Inputs ~N(0,1): fp16 range safe.
// Block: 512 thr / 16 warps; warp = m16 tile; block = 256 positions;
// codes in 2 smem chunks of 256; per (nt,ks16) one LDS.128 feeds 3 MMAs.
// ===========================================================================

static constexpr int C = 64, E = 512, S = 32768;

__device__ float g_partials[512];

#define MMA_F16(acc, a, b0, b1) \
    asm volatile("mma.sync.aligned.m16n8k16.row.col.f32.f16.f16.f32 " \
                 "{%0,%1,%2,%3}, {%4,%5,%6,%7}, {%8,%9}, {%0,%1,%2,%3};" \
                 : "+f"((acc)[0]), "+f"((acc)[1]), "+f"((acc)[2]), "+f"((acc)[3]) \
                 : "r"((a)[0]), "r"((a)[1]), "r"((a)[2]), "r"((a)[3]), \
                   "r"(b0), "r"(b1))

// split v0,v1 into packed fp16 hi pair + packed fp16 residual pair
__device__ __forceinline__ void split_pack(float v0, float v1,
                                           uint32_t& hi, uint32_t& lo)
{
    const __half h0 = __float2half_rn(v0);
    const __half h1 = __float2half_rn(v1);
    const float  r0 = v0 - __half2float(h0);
    const float  r1 = v1 - __half2float(h1);
    const __half g0 = __float2half_rn(r0);
    const __half g1 = __float2half_rn(r1);
    hi = (uint32_t)__half_as_ushort(h0) | ((uint32_t)__half_as_ushort(h1) << 16);
    lo = (uint32_t)__half_as_ushort(g0) | ((uint32_t)__half_as_ushort(g1) << 16);
}

// ---- smem layout (float offsets) ----
static constexpr int OFF_XS  = 0;                    // [256][65]
static constexpr int OFF_B   = 16640;                // 32nt*4ks*32lane*4f = 16384
static constexpr int OFF_WSQ = OFF_B + 16384;        // [512]
static constexpr int OFF_IDX = OFF_WSQ + 512;        // [256] int
static constexpr int OFF_RED = OFF_IDX + 256;        // [512]
static constexpr int SMEM_FLOATS = OFF_RED + 512;    // 34304 -> 137216 B

// ===========================================================================
__global__ void __launch_bounds__(512, 1) vq_hmma_kernel(
    const float* __restrict__ x, const float* __restrict__ w,
    float* __restrict__ out_q, float* __restrict__ out_idx)
{
    extern __shared__ float smem[];
    float* xs   = smem + OFF_XS;
    uint4* bbuf = (uint4*)(smem + OFF_B);
    float* wsqs = smem + OFF_WSQ;
    int*   idxb = (int*)(smem + OFF_IDX);
    float* redb = smem + OFF_RED;

    const int tid = threadIdx.x;
    const int l   = tid & 31;
    const int wid = tid >> 5;           // 0..15
    const int wp  = wid * 16;           // warp's first position (local)

    const int p0 = blockIdx.x * 256;
    const int b  = p0 >> 15;
    const int s0 = p0 & (S - 1);
    const float* xb = x + (size_t)b * C * S + s0;

    // ---- x tile -> smem [pos][ch], coalesced ----
    #pragma unroll
    for (int it = 0; it < 32; ++it) {
        const int e  = it * 512 + tid;
        const int k  = e >> 8;
        const int pl = e & 255;
        xs[pl * 65 + k] = xb[(size_t)k * S + pl];
    }
    // ---- wsq (one code per thread) ----
    {
        const float4* wr = (const float4*)(w + tid * C);
        float s = 0.f;
        #pragma unroll
        for (int q = 0; q < 16; ++q) {
            const float4 f = wr[q];
            s = fmaf(f.x, f.x, s); s = fmaf(f.y, f.y, s);
            s = fmaf(f.z, f.z, s); s = fmaf(f.w, f.w, s);
        }
        wsqs[tid] = s;
    }
    __syncthreads();

    // ---- A fragments (fp16 hi/lo), resident: 4 ksteps x 4 regs each ----
    uint32_t Ahi[4][4], Alo[4][4];
    {
        const int r0 = wp + (l >> 2);
        const int r1 = r0 + 8;
        #pragma unroll
        for (int ks = 0; ks < 4; ++ks) {
            const int k0 = ks * 16 + ((l & 3) << 1);
            split_pack(xs[r0 * 65 + k0],     xs[r0 * 65 + k0 + 1], Ahi[ks][0], Alo[ks][0]);
            split_pack(xs[r1 * 65 + k0],     xs[r1 * 65 + k0 + 1], Ahi[ks][1], Alo[ks][1]);
            split_pack(xs[r0 * 65 + k0 + 8], xs[r0 * 65 + k0 + 9], Ahi[ks][2], Alo[ks][2]);
            split_pack(xs[r1 * 65 + k0 + 8], xs[r1 * 65 + k0 + 9], Ahi[ks][3], Alo[ks][3]);
        }
    }

    float bv0 = 3.4e38f, bv1 = 3.4e38f;
    int   bj0 = 0,       bj1 = 0;

    // ---- 2 chunks of 256 codes ----
    #pragma unroll 1
    for (int chunk = 0; chunk < 2; ++chunk) {
        const int base = chunk * 256;
        __syncthreads();   // previous chunk's readers done

        // fill B: slot = (nt*4+ks)*32+lane -> uint4{bhi0,bhi1,blo0,blo1}
        // b0 covers k = k0,k0+1 ; b1 covers k0+8,k0+9 (k0 = ks*16+(lane%4)*2)
        #pragma unroll
        for (int it = 0; it < 8; ++it) {
            const int slot = it * 512 + tid;
            const int lane = slot & 31;
            const int ks   = (slot >> 5) & 3;
            const int nt   = slot >> 7;
            const int code = base + nt * 8 + (lane >> 2);
            const int k0   = ks * 16 + ((lane & 3) << 1);
            const float* wr = w + code * C + k0;
            uint32_t h0, g0, h1, g1;
            split_pack(wr[0], wr[1], h0, g0);
            split_pack(wr[8], wr[9], h1, g1);
            bbuf[slot] = make_uint4(h0, h1, g0, g1);
        }
        __syncthreads();

        #pragma unroll 2
        for (int nt = 0; nt < 32; ++nt) {
            float accA[4] = {0.f, 0.f, 0.f, 0.f};   // hi*hi
            float accB[4] = {0.f, 0.f, 0.f, 0.f};   // hi*lo
            float accC[4] = {0.f, 0.f, 0.f, 0.f};   // lo*hi
            #pragma unroll
            for (int ks = 0; ks < 4; ++ks) {
                const uint4 bq = bbuf[(nt * 4 + ks) * 32 + l];
                MMA_F16(accA, Ahi[ks], bq.x, bq.y);
                MMA_F16(accB, Ahi[ks], bq.z, bq.w);
                MMA_F16(accC, Alo[ks], bq.x, bq.y);
            }
            // fold: scores for 2 codes x 2 position-rows
            const int cb = base + nt * 8 + ((l & 3) << 1);
            const float wq0 = wsqs[cb], wq1 = wsqs[cb + 1];
            const float d0 = accA[0] + accB[0] + accC[0];
            const float d1 = accA[1] + accB[1] + accC[1];
            const float d2 = accA[2] + accB[2] + accC[2];
            const float d3 = accA[3] + accB[3] + accC[3];
            const float sc0 = fmaf(-2.f, d0, wq0);
            const float sc1 = fmaf(-2.f, d1, wq1);
            const float sc2 = fmaf(-2.f, d2, wq0);
            const float sc3 = fmaf(-2.f, d3, wq1);
            {   // row l/4
                const int   jm = (sc1 < sc0) ? cb + 1 : cb;   // tie -> lower j
                const float sm = fminf(sc0, sc1);
                bj0 = (sm < bv0) ? jm : bj0;                  // tie -> keep earlier
                bv0 = fminf(bv0, sm);
            }
            {   // row l/4+8
                const int   jm = (sc3 < sc2) ? cb + 1 : cb;
                const float sm = fminf(sc2, sc3);
                bj1 = (sm < bv1) ? jm : bj1;
                bv1 = fminf(bv1, sm);
            }
        }
    }

    // ---- cross-lane argmin over the quad (cols split across l%4) ----
    #pragma unroll
    for (int off = 1; off <= 2; off <<= 1) {
        float ov; int oj;
        ov = __shfl_xor_sync(0xffffffffu, bv0, off);
        oj = __shfl_xor_sync(0xffffffffu, bj0, off);
        if (ov < bv0 || (ov == bv0 && oj < bj0)) { bv0 = ov; bj0 = oj; }
        ov = __shfl_xor_sync(0xffffffffu, bv1, off);
        oj = __shfl_xor_sync(0xffffffffu, bj1, off);
        if (ov < bv1 || (ov == bv1 && oj < bj1)) { bv1 = ov; bj1 = oj; }
    }
    if ((l & 3) == 0) {
        idxb[wp + (l >> 2)]     = bj0;
        idxb[wp + (l >> 2) + 8] = bj1;
    }
    __syncthreads();

    // ---- epilogue: 2 threads per position, 32 channels each ----
    const int pos = tid & 255;
    const int co  = (tid >> 8) * 32;
    const int j   = idxb[pos];
    if (tid < 256) out_idx[p0 + pos] = (float)j;

    float acc = 0.f;
    const float4* wr = (const float4*)(w + j * C + co);
    float* qb = out_q + (size_t)b * C * S + (size_t)co * S + s0 + pos;
    #pragma unroll
    for (int q4 = 0; q4 < 8; ++q4) {
        const float4 f = wr[q4];
        const float qv[4] = {f.x, f.y, f.z, f.w};
        #pragma unroll
        for (int u = 0; u < 4; ++u) {
            const int c = q4 * 4 + u;
            const float xv = xs[pos * 65 + co + c];
            const float d = qv[u] - xv;
            qb[(size_t)c * S] = d + xv;    // fl(fl(w-x)+x)
            acc = fmaf(d, d, acc);
        }
    }

    redb[tid] = acc;
    __syncthreads();
    #pragma unroll
    for (int off = 256; off > 0; off >>= 1) {
        if (tid < off) redb[tid] += redb[tid + off];
        __syncthreads();
    }
    if (tid == 0) g_partials[blockIdx.x] = redb[0];
}

// ---------------------------------------------------------------------------
__global__ void __launch_bounds__(256) loss_final_kernel(
    float* __restrict__ out_loss, int nblocks, float inv_n)
{
    __shared__ float red[256];
    const int tid = threadIdx.x;
    float a = 0.f;
    for (int i = tid; i < nblocks; i += 256) a += g_partials[i];
    red[tid] = a;
    __syncthreads();
    #pragma unroll
    for (int off = 128; off > 0; off >>= 1) {
        if (tid < off) red[tid] += red[tid + off];
        __syncthreads();
    }
    if (tid == 0) out_loss[0] = 0.25f * red[0] * inv_n;
}

// ---------------------------------------------------------------------------
extern "C" void kernel_launch(void* const* d_in, const int* in_sizes, int n_in,
                              void* d_out, int out_size)
{
    const float* x = (const float*)d_in[0];
    const float* w = (const float*)d_in[1];
    float* out = (float*)d_out;

    const int n_x  = in_sizes[0];   // 8388608
    const int npos = n_x / C;       // 131072

    float* out_q    = out;
    float* out_idx  = out + n_x;
    float* out_loss = out + n_x + npos;

    const int smem_bytes = SMEM_FLOATS * (int)sizeof(float);  // 137216
    cudaFuncSetAttribute(vq_hmma_kernel,
                         cudaFuncAttributeMaxDynamicSharedMemorySize, smem_bytes);

    const int blocks = npos / 256;   // 512
    vq_hmma_kernel<<<blocks, 512, smem_bytes>>>(x, w, out_q, out_idx);
    loss_final_kernel<<<1, 256>>>(out_loss, blocks, 1.0f / (float)n_x);
}

// round 10
// speedup vs baseline: 4.3839x; 1.2683x over previous
#include <cuda_runtime.h>
#include <cuda_fp16.h>
#include <cstdint>

// ===========================================================================
// VQ-VAE quantizer — fp16 2-split mma.sync m16n8k16 argmin-GEMM (round 10).
//   x [4,64,32,32,32] fp32, weight [512,64] fp32
// out: quantized_st (8.4M), embed_idx (131072 as float), latent_loss (1)
//
// score_j = wsq_j - 2*dot(x,w_j); dot = Ahi*Bhi + Ahi*Blo + Alo*Bhi (fp16
// 2-split, fp32 acc) with all three passes CHAINED into one accumulator.
// Codebook split + B-fragment layout + wsq precomputed once in prep kernel.
// Block: 512 thr / 16 warps; warp = m16 tile; block = 256 positions.
// ===========================================================================

static constexpr int C = 64, E = 512, S = 32768;

__device__ float g_partials[512];
__device__ float g_wsq[E];
__device__ uint4 g_bfrag[8192];   // (nt*4+ks)*32+lane : {hi0,hi1,lo0,lo1}

#define MMA_F16(acc, a, b0, b1) \
    asm volatile("mma.sync.aligned.m16n8k16.row.col.f32.f16.f16.f32 " \
                 "{%0,%1,%2,%3}, {%4,%5,%6,%7}, {%8,%9}, {%0,%1,%2,%3};" \
                 : "+f"((acc)[0]), "+f"((acc)[1]), "+f"((acc)[2]), "+f"((acc)[3]) \
                 : "r"((a)[0]), "r"((a)[1]), "r"((a)[2]), "r"((a)[3]), \
                   "r"(b0), "r"(b1))

__device__ __forceinline__ void split_pack(float v0, float v1,
                                           uint32_t& hi, uint32_t& lo)
{
    const __half h0 = __float2half_rn(v0);
    const __half h1 = __float2half_rn(v1);
    const float  r0 = v0 - __half2float(h0);
    const float  r1 = v1 - __half2float(h1);
    const __half g0 = __float2half_rn(r0);
    const __half g1 = __float2half_rn(r1);
    hi = (uint32_t)__half_as_ushort(h0) | ((uint32_t)__half_as_ushort(h1) << 16);
    lo = (uint32_t)__half_as_ushort(g0) | ((uint32_t)__half_as_ushort(g1) << 16);
}

// ---- smem layout (float offsets) ----
static constexpr int OFF_XS  = 0;                    // [256][65]
static constexpr int OFF_B   = 16640;                // 4096 uint4 = 16384 floats
static constexpr int OFF_WSQ = OFF_B + 16384;        // [512]
static constexpr int OFF_IDX = OFF_WSQ + 512;        // [256] int
static constexpr int OFF_RED = OFF_IDX + 256;        // [512]
static constexpr int SMEM_FLOATS = OFF_RED + 512;    // 34304 -> 137216 B

// ---------------------------------------------------------------------------
// Prep: split codebook into B-fragment layout + wsq. 16 blocks x 512 thr.
// ---------------------------------------------------------------------------
__global__ void __launch_bounds__(512) prep_kernel(const float* __restrict__ w)
{
    const int sl = blockIdx.x * 512 + threadIdx.x;   // 0..8191
    const int lane = sl & 31;
    const int ks   = (sl >> 5) & 3;
    const int nt   = sl >> 7;
    const int code = nt * 8 + (lane >> 2);
    const int k0   = ks * 16 + ((lane & 3) << 1);
    const float* wr = w + code * C + k0;
    uint32_t h0, g0, h1, g1;
    split_pack(wr[0], wr[1], h0, g0);
    split_pack(wr[8], wr[9], h1, g1);
    g_bfrag[sl] = make_uint4(h0, h1, g0, g1);

    if (sl < E) {
        const float4* r = (const float4*)(w + sl * C);
        float s = 0.f;
        #pragma unroll
        for (int q = 0; q < 16; ++q) {
            const float4 f = r[q];
            s = fmaf(f.x, f.x, s); s = fmaf(f.y, f.y, s);
            s = fmaf(f.z, f.z, s); s = fmaf(f.w, f.w, s);
        }
        g_wsq[sl] = s;
    }
}

// ===========================================================================
__global__ void __launch_bounds__(512, 1) vq_hmma_kernel(
    const float* __restrict__ x, const float* __restrict__ w,
    float* __restrict__ out_q, float* __restrict__ out_idx)
{
    extern __shared__ float smem[];
    float* xs   = smem + OFF_XS;
    uint4* bbuf = (uint4*)(smem + OFF_B);
    float* wsqs = smem + OFF_WSQ;
    int*   idxb = (int*)(smem + OFF_IDX);
    float* redb = smem + OFF_RED;

    const int tid = threadIdx.x;
    const int l   = tid & 31;
    const int wid = tid >> 5;           // 0..15
    const int wp  = wid * 16;           // warp's first position (local)

    const int p0 = blockIdx.x * 256;
    const int b  = p0 >> 15;
    const int s0 = p0 & (S - 1);
    const float* xb = x + (size_t)b * C * S + s0;

    // ---- x tile -> smem [pos][ch], coalesced ----
    #pragma unroll
    for (int it = 0; it < 32; ++it) {
        const int e  = it * 512 + tid;
        const int k  = e >> 8;
        const int pl = e & 255;
        xs[pl * 65 + k] = xb[(size_t)k * S + pl];
    }
    wsqs[tid] = g_wsq[tid];
    __syncthreads();

    // ---- A fragments (fp16 hi/lo), resident ----
    uint32_t Ahi[4][4], Alo[4][4];
    {
        const int r0 = wp + (l >> 2);
        const int r1 = r0 + 8;
        #pragma unroll
        for (int ks = 0; ks < 4; ++ks) {
            const int k0 = ks * 16 + ((l & 3) << 1);
            split_pack(xs[r0 * 65 + k0],     xs[r0 * 65 + k0 + 1], Ahi[ks][0], Alo[ks][0]);
            split_pack(xs[r1 * 65 + k0],     xs[r1 * 65 + k0 + 1], Ahi[ks][1], Alo[ks][1]);
            split_pack(xs[r0 * 65 + k0 + 8], xs[r0 * 65 + k0 + 9], Ahi[ks][2], Alo[ks][2]);
            split_pack(xs[r1 * 65 + k0 + 8], xs[r1 * 65 + k0 + 9], Ahi[ks][3], Alo[ks][3]);
        }
    }

    float bv0 = 3.4e38f, bv1 = 3.4e38f;
    int   bj0 = 0,       bj1 = 0;

    // ---- 2 chunks of 256 codes ----
    #pragma unroll 1
    for (int chunk = 0; chunk < 2; ++chunk) {
        const int base = chunk * 256;
        __syncthreads();   // previous chunk's readers done

        // fill B: raw copy from precomputed fragment buffer (L2-resident)
        {
            const uint4* src = g_bfrag + chunk * 4096;
            #pragma unroll
            for (int it = 0; it < 8; ++it)
                bbuf[it * 512 + tid] = src[it * 512 + tid];
        }
        __syncthreads();

        #pragma unroll 2
        for (int nt = 0; nt < 32; ++nt) {
            float acc[4] = {0.f, 0.f, 0.f, 0.f};
            #pragma unroll
            for (int ks = 0; ks < 4; ++ks) {
                const uint4 bq = bbuf[(nt * 4 + ks) * 32 + l];
                MMA_F16(acc, Ahi[ks], bq.x, bq.y);   // hi*hi
                MMA_F16(acc, Ahi[ks], bq.z, bq.w);   // hi*lo
                MMA_F16(acc, Alo[ks], bq.x, bq.y);   // lo*hi
            }
            // fold: scores for 2 codes x 2 position-rows
            const int cb = base + nt * 8 + ((l & 3) << 1);
            const float wq0 = wsqs[cb], wq1 = wsqs[cb + 1];
            const float sc0 = fmaf(-2.f, acc[0], wq0);
            const float sc1 = fmaf(-2.f, acc[1], wq1);
            const float sc2 = fmaf(-2.f, acc[2], wq0);
            const float sc3 = fmaf(-2.f, acc[3], wq1);
            {   // row l/4
                const int   jm = (sc1 < sc0) ? cb + 1 : cb;   // tie -> lower j
                const float sm = fminf(sc0, sc1);
                bj0 = (sm < bv0) ? jm : bj0;                  // tie -> keep earlier
                bv0 = fminf(bv0, sm);
            }
            {   // row l/4+8
                const int   jm = (sc3 < sc2) ? cb + 1 : cb;
                const float sm = fminf(sc2, sc3);
                bj1 = (sm < bv1) ? jm : bj1;
                bv1 = fminf(bv1, sm);
            }
        }
    }

    // ---- cross-lane argmin over the quad (cols split across l%4) ----
    #pragma unroll
    for (int off = 1; off <= 2; off <<= 1) {
        float ov; int oj;
        ov = __shfl_xor_sync(0xffffffffu, bv0, off);
        oj = __shfl_xor_sync(0xffffffffu, bj0, off);
        if (ov < bv0 || (ov == bv0 && oj < bj0)) { bv0 = ov; bj0 = oj; }
        ov = __shfl_xor_sync(0xffffffffu, bv1, off);
        oj = __shfl_xor_sync(0xffffffffu, bj1, off);
        if (ov < bv1 || (ov == bv1 && oj < bj1)) { bv1 = ov; bj1 = oj; }
    }
    if ((l & 3) == 0) {
        idxb[wp + (l >> 2)]     = bj0;
        idxb[wp + (l >> 2) + 8] = bj1;
    }
    __syncthreads();

    // ---- epilogue: 2 threads per position, 32 channels each ----
    const int pos = tid & 255;
    const int co  = (tid >> 8) * 32;
    const int j   = idxb[pos];
    if (tid < 256) out_idx[p0 + pos] = (float)j;

    float acc = 0.f;
    const float4* wr = (const float4*)(w + j * C + co);
    float* qb = out_q + (size_t)b * C * S + (size_t)co * S + s0 + pos;
    #pragma unroll
    for (int q4 = 0; q4 < 8; ++q4) {
        const float4 f = wr[q4];
        const float qv[4] = {f.x, f.y, f.z, f.w};
        #pragma unroll
        for (int u = 0; u < 4; ++u) {
            const int c = q4 * 4 + u;
            const float xv = xs[pos * 65 + co + c];
            const float d = qv[u] - xv;
            qb[(size_t)c * S] = d + xv;    // fl(fl(w-x)+x)
            acc = fmaf(d, d, acc);
        }
    }

    redb[tid] = acc;
    __syncthreads();
    #pragma unroll
    for (int off = 256; off > 0; off >>= 1) {
        if (tid < off) redb[tid] += redb[tid + off];
        __syncthreads();
    }
    if (tid == 0) g_partials[blockIdx.x] = redb[0];
}

// ---------------------------------------------------------------------------
__global__ void __launch_bounds__(256) loss_final_kernel(
    float* __restrict__ out_loss, int nblocks, float inv_n)
{
    __shared__ float red[256];
    const int tid = threadIdx.x;
    float a = 0.f;
    for (int i = tid; i < nblocks; i += 256) a += g_partials[i];
    red[tid] = a;
    __syncthreads();
    #pragma unroll
    for (int off = 128; off > 0; off >>= 1) {
        if (tid < off) red[tid] += red[tid + off];
        __syncthreads();
    }
    if (tid == 0) out_loss[0] = 0.25f * red[0] * inv_n;
}

// ---------------------------------------------------------------------------
extern "C" void kernel_launch(void* const* d_in, const int* in_sizes, int n_in,
                              void* d_out, int out_size)
{
    const float* x = (const float*)d_in[0];
    const float* w = (const float*)d_in[1];
    float* out = (float*)d_out;

    const int n_x  = in_sizes[0];   // 8388608
    const int npos = n_x / C;       // 131072

    float* out_q    = out;
    float* out_idx  = out + n_x;
    float* out_loss = out + n_x + npos;

    const int smem_bytes = SMEM_FLOATS * (int)sizeof(float);  // 137216
    cudaFuncSetAttribute(vq_hmma_kernel,
                         cudaFuncAttributeMaxDynamicSharedMemorySize, smem_bytes);

    prep_kernel<<<16, 512>>>(w);
    const int blocks = npos / 256;   // 512
    vq_hmma_kernel<<<blocks, 512, smem_bytes>>>(x, w, out_q, out_idx);
    loss_final_kernel<<<1, 256>>>(out_loss, blocks, 1.0f / (float)n_x);
}

// round 11
// speedup vs baseline: 4.6680x; 1.0648x over previous
#include <cuda_runtime.h>
#include <cuda_fp16.h>
#include <cstdint>

// ===========================================================================
// VQ-VAE quantizer — fp16 2-split mma.sync m16n8k16 argmin-GEMM (round 11).
//   x [4,64,32,32,32] fp32, weight [512,64] fp32
// out: quantized_st (8.4M), embed_idx (131072 as float), latent_loss (1)
//
// score_j = wsq_j - 2*dot(x,w_j); dot = Ahi*Bhi + Ahi*Blo + Alo*Bhi (fp16
// 2-split, fp32 acc, chained). Round 11: 2 M-tiles per warp (32 pos) ->
// each B LDS.128 feeds 6 MMAs, 4 indep chains/warp; block = 512 positions;
// loss final reduction fused via last-block pattern; prep at 64 blocks.
// ===========================================================================

static constexpr int C = 64, E = 512, S = 32768;

__device__ float    g_partials[256];
__device__ float    g_wsq[E];
__device__ uint4    g_bfrag[8192];   // (nt*4+ks)*32+lane : {hi0,hi1,lo0,lo1}
__device__ unsigned g_count = 0;

#define MMA_F16(acc, a, b0, b1) \
    asm volatile("mma.sync.aligned.m16n8k16.row.col.f32.f16.f16.f32 " \
                 "{%0,%1,%2,%3}, {%4,%5,%6,%7}, {%8,%9}, {%0,%1,%2,%3};" \
                 : "+f"((acc)[0]), "+f"((acc)[1]), "+f"((acc)[2]), "+f"((acc)[3]) \
                 : "r"((a)[0]), "r"((a)[1]), "r"((a)[2]), "r"((a)[3]), \
                   "r"(b0), "r"(b1))

__device__ __forceinline__ void split_pack(float v0, float v1,
                                           uint32_t& hi, uint32_t& lo)
{
    const __half h0 = __float2half_rn(v0);
    const __half h1 = __float2half_rn(v1);
    const float  r0 = v0 - __half2float(h0);
    const float  r1 = v1 - __half2float(h1);
    const __half g0 = __float2half_rn(r0);
    const __half g1 = __float2half_rn(r1);
    hi = (uint32_t)__half_as_ushort(h0) | ((uint32_t)__half_as_ushort(h1) << 16);
    lo = (uint32_t)__half_as_ushort(g0) | ((uint32_t)__half_as_ushort(g1) << 16);
}

// ---- smem layout (float offsets) ----
static constexpr int OFF_XS  = 0;                   // [512][65] = 33280
static constexpr int OFF_B   = 33280;               // 4096 uint4 = 16384
static constexpr int OFF_WSQ = OFF_B + 16384;       // [512]
static constexpr int OFF_IDX = OFF_WSQ + 512;       // [512] int
static constexpr int OFF_RED = OFF_IDX + 512;       // [512]
static constexpr int SMEM_FLOATS = OFF_RED + 512;   // 51200 -> 204800 B

// ---------------------------------------------------------------------------
// Prep: split codebook into B-fragment layout + wsq. 64 blocks x 128 thr.
// ---------------------------------------------------------------------------
__global__ void __launch_bounds__(128) prep_kernel(const float* __restrict__ w)
{
    const int sl = blockIdx.x * 128 + threadIdx.x;   // 0..8191
    const int lane = sl & 31;
    const int ks   = (sl >> 5) & 3;
    const int nt   = sl >> 7;
    const int code = nt * 8 + (lane >> 2);
    const int k0   = ks * 16 + ((lane & 3) << 1);
    const float* wr = w + code * C + k0;
    uint32_t h0, g0, h1, g1;
    split_pack(wr[0], wr[1], h0, g0);
    split_pack(wr[8], wr[9], h1, g1);
    g_bfrag[sl] = make_uint4(h0, h1, g0, g1);

    if (sl < E) {
        const float4* r = (const float4*)(w + sl * C);
        float s = 0.f;
        #pragma unroll
        for (int q = 0; q < 16; ++q) {
            const float4 f = r[q];
            s = fmaf(f.x, f.x, s); s = fmaf(f.y, f.y, s);
            s = fmaf(f.z, f.z, s); s = fmaf(f.w, f.w, s);
        }
        g_wsq[sl] = s;
    }
}

// ===========================================================================
__global__ void __launch_bounds__(512, 1) vq_hmma_kernel(
    const float* __restrict__ x, const float* __restrict__ w,
    float* __restrict__ out_q, float* __restrict__ out_idx,
    float* __restrict__ out_loss, float inv_n)
{
    extern __shared__ float smem[];
    float* xs   = smem + OFF_XS;
    uint4* bbuf = (uint4*)(smem + OFF_B);
    float* wsqs = smem + OFF_WSQ;
    int*   idxb = (int*)(smem + OFF_IDX);
    float* redb = smem + OFF_RED;
    __shared__ int is_last;

    const int tid = threadIdx.x;
    const int l   = tid & 31;
    const int wid = tid >> 5;           // 0..15
    const int wp  = wid * 32;           // warp's first position (local)

    const int p0 = blockIdx.x * 512;
    const int b  = p0 >> 15;
    const int s0 = p0 & (S - 1);
    const float* xb = x + (size_t)b * C * S + s0;

    // ---- x tile -> smem [pos][ch], coalesced ----
    #pragma unroll 8
    for (int it = 0; it < 64; ++it) {
        const int e  = it * 512 + tid;
        const int k  = e >> 9;
        const int pl = e & 511;
        xs[pl * 65 + k] = xb[(size_t)k * S + pl];
    }
    wsqs[tid] = g_wsq[tid];
    __syncthreads();

    // ---- A fragments (fp16 hi/lo): 2 M-tiles, 4 ksteps x 4 regs each ----
    uint32_t Ahi0[4][4], Alo0[4][4], Ahi1[4][4], Alo1[4][4];
    {
        const int r0 = wp + (l >> 2);
        #pragma unroll
        for (int ks = 0; ks < 4; ++ks) {
            const int k0 = ks * 16 + ((l & 3) << 1);
            split_pack(xs[r0 * 65 + k0],            xs[r0 * 65 + k0 + 1],        Ahi0[ks][0], Alo0[ks][0]);
            split_pack(xs[(r0 + 8) * 65 + k0],      xs[(r0 + 8) * 65 + k0 + 1],  Ahi0[ks][1], Alo0[ks][1]);
            split_pack(xs[r0 * 65 + k0 + 8],        xs[r0 * 65 + k0 + 9],        Ahi0[ks][2], Alo0[ks][2]);
            split_pack(xs[(r0 + 8) * 65 + k0 + 8],  xs[(r0 + 8) * 65 + k0 + 9],  Ahi0[ks][3], Alo0[ks][3]);
            split_pack(xs[(r0 + 16) * 65 + k0],     xs[(r0 + 16) * 65 + k0 + 1], Ahi1[ks][0], Alo1[ks][0]);
            split_pack(xs[(r0 + 24) * 65 + k0],     xs[(r0 + 24) * 65 + k0 + 1], Ahi1[ks][1], Alo1[ks][1]);
            split_pack(xs[(r0 + 16) * 65 + k0 + 8], xs[(r0 + 16) * 65 + k0 + 9], Ahi1[ks][2], Alo1[ks][2]);
            split_pack(xs[(r0 + 24) * 65 + k0 + 8], xs[(r0 + 24) * 65 + k0 + 9], Ahi1[ks][3], Alo1[ks][3]);
        }
    }

    float bv0 = 3.4e38f, bv1 = 3.4e38f, bv2 = 3.4e38f, bv3 = 3.4e38f;
    int   bj0 = 0,       bj1 = 0,       bj2 = 0,       bj3 = 0;

    // ---- 2 chunks of 256 codes ----
    #pragma unroll 1
    for (int chunk = 0; chunk < 2; ++chunk) {
        const int base = chunk * 256;
        __syncthreads();   // previous chunk's readers done

        // fill B: raw copy from precomputed fragment buffer (L2-resident)
        {
            const uint4* src = g_bfrag + chunk * 4096;
            #pragma unroll
            for (int it = 0; it < 8; ++it)
                bbuf[it * 512 + tid] = src[it * 512 + tid];
        }
        __syncthreads();

        #pragma unroll 2
        for (int nt = 0; nt < 32; ++nt) {
            float a0[4] = {0.f, 0.f, 0.f, 0.f};   // M-tile 0
            float a1[4] = {0.f, 0.f, 0.f, 0.f};   // M-tile 1
            #pragma unroll
            for (int ks = 0; ks < 4; ++ks) {
                const uint4 bq = bbuf[(nt * 4 + ks) * 32 + l];
                MMA_F16(a0, Ahi0[ks], bq.x, bq.y);   // hi*hi
                MMA_F16(a1, Ahi1[ks], bq.x, bq.y);
                MMA_F16(a0, Ahi0[ks], bq.z, bq.w);   // hi*lo
                MMA_F16(a1, Ahi1[ks], bq.z, bq.w);
                MMA_F16(a0, Alo0[ks], bq.x, bq.y);   // lo*hi
                MMA_F16(a1, Alo1[ks], bq.x, bq.y);
            }
            const int cb = base + nt * 8 + ((l & 3) << 1);
            const float wq0 = wsqs[cb], wq1 = wsqs[cb + 1];
            // M-tile 0: rows l/4, l/4+8
            {
                const float sc0 = fmaf(-2.f, a0[0], wq0);
                const float sc1 = fmaf(-2.f, a0[1], wq1);
                const float sc2 = fmaf(-2.f, a0[2], wq0);
                const float sc3 = fmaf(-2.f, a0[3], wq1);
                int   jm = (sc1 < sc0) ? cb + 1 : cb;     // tie -> lower j
                float sm = fminf(sc0, sc1);
                bj0 = (sm < bv0) ? jm : bj0;  bv0 = fminf(bv0, sm);
                jm = (sc3 < sc2) ? cb + 1 : cb;
                sm = fminf(sc2, sc3);
                bj1 = (sm < bv1) ? jm : bj1;  bv1 = fminf(bv1, sm);
            }
            // M-tile 1: rows l/4+16, l/4+24
            {
                const float sc0 = fmaf(-2.f, a1[0], wq0);
                const float sc1 = fmaf(-2.f, a1[1], wq1);
                const float sc2 = fmaf(-2.f, a1[2], wq0);
                const float sc3 = fmaf(-2.f, a1[3], wq1);
                int   jm = (sc1 < sc0) ? cb + 1 : cb;
                float sm = fminf(sc0, sc1);
                bj2 = (sm < bv2) ? jm : bj2;  bv2 = fminf(bv2, sm);
                jm = (sc3 < sc2) ? cb + 1 : cb;
                sm = fminf(sc2, sc3);
                bj3 = (sm < bv3) ? jm : bj3;  bv3 = fminf(bv3, sm);
            }
        }
    }

    // ---- cross-lane argmin over quads (cols split across l%4) ----
    #pragma unroll
    for (int off = 1; off <= 2; off <<= 1) {
        float ov; int oj;
        ov = __shfl_xor_sync(0xffffffffu, bv0, off);
        oj = __shfl_xor_sync(0xffffffffu, bj0, off);
        if (ov < bv0 || (ov == bv0 && oj < bj0)) { bv0 = ov; bj0 = oj; }
        ov = __shfl_xor_sync(0xffffffffu, bv1, off);
        oj = __shfl_xor_sync(0xffffffffu, bj1, off);
        if (ov < bv1 || (ov == bv1 && oj < bj1)) { bv1 = ov; bj1 = oj; }
        ov = __shfl_xor_sync(0xffffffffu, bv2, off);
        oj = __shfl_xor_sync(0xffffffffu, bj2, off);
        if (ov < bv2 || (ov == bv2 && oj < bj2)) { bv2 = ov; bj2 = oj; }
        ov = __shfl_xor_sync(0xffffffffu, bv3, off);
        oj = __shfl_xor_sync(0xffffffffu, bj3, off);
        if (ov < bv3 || (ov == bv3 && oj < bj3)) { bv3 = ov; bj3 = oj; }
    }
    if ((l & 3) == 0) {
        const int r = l >> 2;
        idxb[wp + r]      = bj0;
        idxb[wp + r + 8]  = bj1;
        idxb[wp + r + 16] = bj2;
        idxb[wp + r + 24] = bj3;
    }
    __syncthreads();

    // ---- epilogue: 1 thread per position, 64 channels ----
    const int pos = tid;
    const int j   = idxb[pos];
    out_idx[p0 + pos] = (float)j;

    float acc = 0.f;
    const float4* wr = (const float4*)(w + j * C);
    float* qb = out_q + (size_t)b * C * S + s0 + pos;
    #pragma unroll 4
    for (int q4 = 0; q4 < 16; ++q4) {
        const float4 f = wr[q4];
        const float qv[4] = {f.x, f.y, f.z, f.w};
        #pragma unroll
        for (int u = 0; u < 4; ++u) {
            const int c = q4 * 4 + u;
            const float xv = xs[pos * 65 + c];
            const float d = qv[u] - xv;
            qb[(size_t)c * S] = d + xv;    // fl(fl(w-x)+x)
            acc = fmaf(d, d, acc);
        }
    }

    redb[tid] = acc;
    __syncthreads();
    #pragma unroll
    for (int off = 256; off > 0; off >>= 1) {
        if (tid < off) redb[tid] += redb[tid + off];
        __syncthreads();
    }

    // ---- fused deterministic loss finalization (last block) ----
    if (tid == 0) {
        g_partials[blockIdx.x] = redb[0];
        __threadfence();
        const unsigned t = atomicAdd(&g_count, 1u);
        is_last = (t == (unsigned)(gridDim.x - 1)) ? 1 : 0;
    }
    __syncthreads();
    if (is_last) {
        __threadfence();   // acquire: all partials visible
        float a = (tid < 256) ? g_partials[tid] : 0.f;
        redb[tid] = a;
        __syncthreads();
        #pragma unroll
        for (int off = 256; off > 0; off >>= 1) {
            if (tid < off) redb[tid] += redb[tid + off];
            __syncthreads();
        }
        if (tid == 0) {
            out_loss[0] = 0.25f * redb[0] * inv_n;
            g_count = 0;   // reset for next graph replay
        }
    }
}

// ---------------------------------------------------------------------------
extern "C" void kernel_launch(void* const* d_in, const int* in_sizes, int n_in,
                              void* d_out, int out_size)
{
    const float* x = (const float*)d_in[0];
    const float* w = (const float*)d_in[1];
    float* out = (float*)d_out;

    const int n_x  = in_sizes[0];   // 8388608
    const int npos = n_x / C;       // 131072

    float* out_q    = out;
    float* out_idx  = out + n_x;
    float* out_loss = out + n_x + npos;

    const int smem_bytes = SMEM_FLOATS * (int)sizeof(float);  // 204800
    cudaFuncSetAttribute(vq_hmma_kernel,
                         cudaFuncAttributeMaxDynamicSharedMemorySize, smem_bytes);

    prep_kernel<<<64, 128>>>(w);
    const int blocks = npos / 512;   // 256
    vq_hmma_kernel<<<blocks, 512, smem_bytes>>>(x, w, out_q, out_idx,
                                                out_loss, 1.0f / (float)n_x);
}